// round 2
// baseline (speedup 1.0000x reference)
#include <cuda_runtime.h>

// Problem constants
#define BB 16
#define NL 4097          // x0 rows per batch
#define NM 1024          // p_m rows
#define DS 256
#define DM 512
#define DL 1024
#define NKV 4098         // cls + NL
#define NCHUNK 65        // ceil(4097/64)
#define MCH 32           // m-chunks for transposed gemv

// ---------------- device scratch (no allocations allowed) ----------------
__device__ float g_csp  [BB*DM];        // cls_s_proj
__device__ float g_q1   [BB*DM];
__device__ float g_qk1  [BB*DM];
__device__ float g_cmp  [BB*DL];        // cls_m_proj
__device__ float g_q2   [BB*DL];
__device__ float g_qk2  [BB*DL];
__device__ float g_sc1  [BB*(NM+1)];    // att1 scores (/22); idx0 handled in soft1
__device__ float g_att1s[BB*(NM+1)];
__device__ float g_a1p  [BB*NKV];       // att1 projected
__device__ float g_PE   [BB*NCHUNK*DL];
__device__ float g_PA   [BB*NCHUNK*DL];
__device__ float g_PZ   [BB*NCHUNK];
__device__ float g_u    [BB*DL];
__device__ float g_outv [BB*DL];
__device__ float g_gs   [BB*DS];
__device__ float g_part [MCH*BB*DL];

// ---------------- multi-batch GEMV: Y[b,m] = bias[m] + W[m,:]·X[b,:] ----------------
__global__ __launch_bounds__(256) void gemvA_kernel(
    const float* __restrict__ W, const float* __restrict__ X,
    int ldx4, const float* __restrict__ bias,
    float* __restrict__ Y, int M, int D)
{
    int m = blockIdx.x * 8 + (threadIdx.x >> 5);
    int lane = threadIdx.x & 31;
    if (m >= M) return;
    const float4* w4 = (const float4*)(W + (size_t)m * D);
    const float4* x4 = (const float4*)X;
    int D4 = D >> 2;
    float acc[BB];
#pragma unroll
    for (int b = 0; b < BB; b++) acc[b] = 0.f;
    for (int f = lane; f < D4; f += 32) {
        float4 w = w4[f];
#pragma unroll
        for (int b = 0; b < BB; b++) {
            float4 x = x4[(size_t)b * ldx4 + f];
            acc[b] += w.x*x.x + w.y*x.y + w.z*x.z + w.w*x.w;
        }
    }
#pragma unroll
    for (int b = 0; b < BB; b++) {
        float v = acc[b];
#pragma unroll
        for (int o = 16; o; o >>= 1) v += __shfl_xor_sync(~0u, v, o);
        if (lane == 0) Y[(size_t)b * M + m] = v + (bias ? bias[m] : 0.f);
    }
}

// ---------------- transposed GEMV partials: Y[b,d] = sum_m W[m,d]*X[b,m] ----------------
__global__ __launch_bounds__(256) void gemvBpart_kernel(
    const float* __restrict__ W, const float* __restrict__ X,
    float* __restrict__ part, int M, int D)
{
    int d = blockIdx.x * 256 + threadIdx.x;
    int rows = M / MCH;                 // 16 or 32
    int m0 = blockIdx.y * rows;
    __shared__ float q[BB * 32];
    for (int idx = threadIdx.x; idx < BB * rows; idx += 256) {
        int bb = idx / rows, mm = idx - bb * rows;
        q[bb * rows + mm] = X[(size_t)bb * M + m0 + mm];
    }
    __syncthreads();
    float acc[BB];
#pragma unroll
    for (int b = 0; b < BB; b++) acc[b] = 0.f;
    for (int mm = 0; mm < rows; mm++) {
        float w = W[(size_t)(m0 + mm) * D + d];
#pragma unroll
        for (int b = 0; b < BB; b++) acc[b] += w * q[b * rows + mm];
    }
#pragma unroll
    for (int b = 0; b < BB; b++)
        part[((size_t)blockIdx.y * BB + b) * D + d] = acc[b];
}

__global__ __launch_bounds__(256) void gemvBred_kernel(
    const float* __restrict__ part, float* __restrict__ Y, int D)
{
    int t = blockIdx.x * 256 + threadIdx.x;
    if (t >= BB * D) return;
    int b = t / D, d = t - b * D;
    float acc = 0.f;
#pragma unroll
    for (int c = 0; c < MCH; c++) acc += part[((size_t)c * BB + b) * D + d];
    Y[t] = acc;
}

// ---------------- att1 scores over p_m ----------------
__global__ __launch_bounds__(256) void score1_kernel(const float* __restrict__ x1)
{
    int gw = (blockIdx.x * blockDim.x + threadIdx.x) >> 5;
    int lane = threadIdx.x & 31;
    int b = gw >> 10, k = gw & 1023;
    const float4* row = (const float4*)(x1 + ((size_t)b * (NM + 1) + 1 + k) * DM);
    const float4* qk  = (const float4*)(g_qk1 + (size_t)b * DM);
    float s = 0.f;
#pragma unroll
    for (int j = 0; j < 4; j++) {
        float4 v = row[lane + 32 * j];
        float4 q = qk [lane + 32 * j];
        s += v.x*q.x + v.y*q.y + v.z*q.z + v.w*q.w;
    }
#pragma unroll
    for (int o = 16; o; o >>= 1) s += __shfl_xor_sync(~0u, s, o);
    if (!lane) g_sc1[(size_t)b * (NM + 1) + 1 + k] = s * (1.f / 22.f);
}

// ---------------- softmax att1 (1025 values/batch; scores O(0.1) -> no max needed) ----------------
__global__ __launch_bounds__(256) void soft1_kernel()
{
    int b = blockIdx.x, t = threadIdx.x;
    __shared__ float red[256];
    __shared__ float ex[NM + 1];
    __shared__ float s0sh;
    float p = 0.f;
    for (int i = t; i < DM; i += 256) p += g_csp[b * DM + i] * g_qk1[b * DM + i];
    red[t] = p; __syncthreads();
    for (int s = 128; s; s >>= 1) { if (t < s) red[t] += red[t + s]; __syncthreads(); }
    if (t == 0) s0sh = red[0] * (1.f / 22.f);
    __syncthreads();
    float zp = 0.f;
    for (int i = t; i < NM + 1; i += 256) {
        float s = (i == 0) ? s0sh : g_sc1[b * (NM + 1) + i];
        float e = __expf(s);
        ex[i] = e; zp += e;
    }
    red[t] = zp; __syncthreads();
    for (int s = 128; s; s >>= 1) { if (t < s) red[t] += red[t + s]; __syncthreads(); }
    float inv = 1.f / red[0];
    for (int i = t; i < NM + 1; i += 256) g_att1s[b * (NM + 1) + i] = ex[i] * inv;
}

// ---------------- att1 projection: a1p[b,j] = proj_b[j] + proj_w[j,:]·att1s[b,:] ----------------
__global__ __launch_bounds__(256) void proj_kernel(
    const float* __restrict__ proj_w, const float* __restrict__ proj_b)
{
    __shared__ float att[8 * (NM + 1)];
    int bg = blockIdx.y;
    for (int idx = threadIdx.x; idx < 8 * (NM + 1); idx += 256) {
        int bb = idx / (NM + 1), i = idx - bb * (NM + 1);
        att[idx] = g_att1s[(size_t)(bg * 8 + bb) * (NM + 1) + i];
    }
    __syncthreads();
    int j = blockIdx.x * 8 + (threadIdx.x >> 5);
    int lane = threadIdx.x & 31;
    if (j >= NKV) return;
    const float* wrow = proj_w + (size_t)j * (NM + 1);
    float acc[8] = {0,0,0,0,0,0,0,0};
    for (int i = lane; i < NM + 1; i += 32) {
        float w = wrow[i];
#pragma unroll
        for (int bb = 0; bb < 8; bb++) acc[bb] += w * att[bb * (NM + 1) + i];
    }
#pragma unroll
    for (int bb = 0; bb < 8; bb++) {
        float v = acc[bb];
#pragma unroll
        for (int o = 16; o; o >>= 1) v += __shfl_xor_sync(~0u, v, o);
        if (!lane) g_a1p[(size_t)(bg * 8 + bb) * NKV + j] = v + proj_b[j];
    }
}

// ---------------- THE fused pass over x0: scores + exp-weighted + att1-weighted sums ----------------
__global__ __launch_bounds__(256) void big_kernel(const float* __restrict__ x0)
{
    int b = blockIdx.y, chunk = blockIdx.x;
    int t = threadIdx.x, warp = t >> 5, lane = t & 31;
    __shared__ float4 qk2s[256];
    __shared__ float4 Es[256], As[256];
    __shared__ float Zs[8];
    qk2s[t] = ((const float4*)(g_qk2 + (size_t)b * DL))[t];
    Es[t] = make_float4(0.f, 0.f, 0.f, 0.f);
    As[t] = make_float4(0.f, 0.f, 0.f, 0.f);
    __syncthreads();

    float4 aE[8], aA[8];
#pragma unroll
    for (int j = 0; j < 8; j++) { aE[j] = make_float4(0,0,0,0); aA[j] = make_float4(0,0,0,0); }
    float zacc = 0.f;
    int k0 = chunk * 64;
    for (int r = warp; r < 64; r += 8) {
        int k = k0 + r;
        if (k >= NL) break;
        const float4* row = (const float4*)(x0 + ((size_t)b * NL + k) * DL);
        float4 v[8];
#pragma unroll
        for (int j = 0; j < 8; j++) v[j] = row[lane + 32 * j];
        float s = 0.f;
#pragma unroll
        for (int j = 0; j < 8; j++) {
            float4 q = qk2s[lane + 32 * j];
            s += v[j].x*q.x + v[j].y*q.y + v[j].z*q.z + v[j].w*q.w;
        }
#pragma unroll
        for (int o = 16; o; o >>= 1) s += __shfl_xor_sync(~0u, s, o);
        float w2 = __expf(s * (1.f / 32.f));
        float w1 = g_a1p[(size_t)b * NKV + k + 1];
        zacc += w2;
#pragma unroll
        for (int j = 0; j < 8; j++) {
            aE[j].x += w2 * v[j].x; aE[j].y += w2 * v[j].y; aE[j].z += w2 * v[j].z; aE[j].w += w2 * v[j].w;
            aA[j].x += w1 * v[j].x; aA[j].y += w1 * v[j].y; aA[j].z += w1 * v[j].z; aA[j].w += w1 * v[j].w;
        }
    }
    // deterministic block combine (serialized warps)
    for (int w = 0; w < 8; w++) {
        if (warp == w) {
#pragma unroll
            for (int j = 0; j < 8; j++) {
                int idx = lane + 32 * j;
                float4 e = Es[idx];
                e.x += aE[j].x; e.y += aE[j].y; e.z += aE[j].z; e.w += aE[j].w;
                Es[idx] = e;
                float4 a = As[idx];
                a.x += aA[j].x; a.y += aA[j].y; a.z += aA[j].z; a.w += aA[j].w;
                As[idx] = a;
            }
            if (lane == 0) Zs[w] = zacc;
        }
        __syncthreads();
    }
    ((float4*)(g_PE + ((size_t)b * NCHUNK + chunk) * DL))[t] = Es[t];
    ((float4*)(g_PA + ((size_t)b * NCHUNK + chunk) * DL))[t] = As[t];
    if (t == 0) {
        float z = 0.f;
#pragma unroll
        for (int w = 0; w < 8; w++) z += Zs[w];
        g_PZ[b * NCHUNK + chunk] = z;
    }
}

// ---------------- combine partials -> u[b,d] ----------------
__global__ __launch_bounds__(1024) void u_kernel()
{
    int b = blockIdx.x, d = threadIdx.x;     // 1024 threads
    __shared__ float red[1024];
    __shared__ float zsh;
    float cmp = g_cmp[b * DL + d];
    float qk  = g_qk2[b * DL + d];
    red[d] = cmp * qk; __syncthreads();
    for (int s = 512; s; s >>= 1) { if (d < s) red[d] += red[d + s]; __syncthreads(); }
    float s2 = red[0] * (1.f / 32.f);
    float ecls = __expf(s2);
    if (d == 0) {
        float z = ecls;
        for (int c = 0; c < NCHUNK; c++) z += g_PZ[b * NCHUNK + c];
        zsh = z;
    }
    __syncthreads();
    float e = 0.f, a = 0.f;
    for (int c = 0; c < NCHUNK; c++) {
        e += g_PE[((size_t)b * NCHUNK + c) * DL + d];
        a += g_PA[((size_t)b * NCHUNK + c) * DL + d];
    }
    float a1p0 = g_a1p[(size_t)b * NKV];
    g_u[b * DL + d] = 0.3f * (a1p0 * cmp + a) + 0.7f * (ecls * cmp + e) / zsh;
}

// ---------------- broadcast g_s to all 4097 output rows ----------------
__global__ __launch_bounds__(256) void write_kernel(float* __restrict__ out)
{
    int b = blockIdx.y;
    int g = threadIdx.x >> 6, l = threadIdx.x & 63;
    float4 val = ((const float4*)(g_gs + b * DS))[l];
    int base = blockIdx.x * 32;
    float4* ob = (float4*)out + (size_t)b * NL * 64;
    int lim = base + 32; if (lim > NL) lim = NL;
    for (int r = base + g; r < lim; r += 4)
        ob[(size_t)r * 64 + l] = val;
}

// ---------------- launch ----------------
extern "C" void kernel_launch(void* const* d_in, const int* in_sizes, int n_in,
                              void* d_out, int out_size)
{
    const float* x0     = (const float*)d_in[0];
    const float* x1     = (const float*)d_in[1];
    const float* x2     = (const float*)d_in[2];
    const float* f_s_w  = (const float*)d_in[3];
    const float* f_s_b  = (const float*)d_in[4];
    const float* f_m_w  = (const float*)d_in[5];
    const float* f_m_b  = (const float*)d_in[6];
    const float* Wq1    = (const float*)d_in[7];
    const float* Wk1    = (const float*)d_in[8];
    const float* Wq2    = (const float*)d_in[9];
    const float* Wk2    = (const float*)d_in[10];
    const float* Wv     = (const float*)d_in[11];
    const float* proj_w = (const float*)d_in[12];
    const float* proj_b = (const float*)d_in[13];
    const float* gs_w   = (const float*)d_in[14];
    const float* gs_b   = (const float*)d_in[15];

    float *p_csp, *p_q1, *p_qk1, *p_cmp, *p_q2, *p_qk2, *p_u, *p_outv, *p_gs, *p_part;
    cudaGetSymbolAddress((void**)&p_csp,  g_csp);
    cudaGetSymbolAddress((void**)&p_q1,   g_q1);
    cudaGetSymbolAddress((void**)&p_qk1,  g_qk1);
    cudaGetSymbolAddress((void**)&p_cmp,  g_cmp);
    cudaGetSymbolAddress((void**)&p_q2,   g_q2);
    cudaGetSymbolAddress((void**)&p_qk2,  g_qk2);
    cudaGetSymbolAddress((void**)&p_u,    g_u);
    cudaGetSymbolAddress((void**)&p_outv, g_outv);
    cudaGetSymbolAddress((void**)&p_gs,   g_gs);
    cudaGetSymbolAddress((void**)&p_part, g_part);

    // small-branch chain (multi-batch GEMVs)
    gemvA_kernel<<<64, 256>>>(f_s_w, x2, (NL * DS) / 4, f_s_b, p_csp, DM, DS);      // cls_s_proj
    gemvA_kernel<<<64, 256>>>(Wq1, p_csp, DM / 4, nullptr, p_q1, DM, DM);           // q1
    gemvBpart_kernel<<<dim3(DM / 256, MCH), 256>>>(Wk1, p_q1, p_part, DM, DM);      // qk1 partials
    gemvBred_kernel<<<(BB * DM) / 256, 256>>>(p_part, p_qk1, DM);
    gemvA_kernel<<<128, 256>>>(f_m_w, x1, ((NM + 1) * DM) / 4, f_m_b, p_cmp, DL, DM); // cls_m_proj
    gemvA_kernel<<<128, 256>>>(Wq2, p_cmp, DL / 4, nullptr, p_q2, DL, DL);          // q2
    gemvBpart_kernel<<<dim3(DL / 256, MCH), 256>>>(Wk2, p_q2, p_part, DL, DL);      // qk2 partials
    gemvBred_kernel<<<(BB * DL) / 256, 256>>>(p_part, p_qk2, DL);

    // att1 branch
    score1_kernel<<<(BB * NM) / 8, 256>>>(x1);
    soft1_kernel<<<BB, 256>>>();
    proj_kernel<<<dim3((NKV + 7) / 8, 2), 256>>>(proj_w, proj_b);

    // fused att2 + weighted-value pass over x0
    big_kernel<<<dim3(NCHUNK, BB), 256>>>(x0);
    u_kernel<<<BB, 1024>>>();

    // epilogue: out = Wv·u ; g_s = gs_w·out + gs_b ; broadcast
    gemvA_kernel<<<128, 256>>>(Wv, p_u, DL / 4, nullptr, p_outv, DL, DL);
    gemvA_kernel<<<32, 256>>>(gs_w, p_outv, DL / 4, gs_b, p_gs, DS, DL);
    write_kernel<<<dim3((NL + 31) / 32, BB), 256>>>((float*)d_out);
}